// round 9
// baseline (speedup 1.0000x reference)
#include <cuda_runtime.h>
#include <cuda_bf16.h>
#include <math.h>
#include <stdint.h>

#define BB 512
#define SS 64
#define TT 32
#define VV 128
#define EE 256
#define HH 512
#define DENC 1024
#define G4H 2048
#define EOS_IDX 2
#define PCOL (HH + DENC)  /* 1536 */

// ---------------- scratch (device globals; no allocations) ----------------
__device__ __nv_bfloat16 g_encproj_bf[(size_t)BB * SS * HH];  // 32 MB (score path)
__device__ float g_pred[(size_t)BB * TT * PCOL];       // 100 MB  [h1n | context]
__device__ float g_Wc0[G4H * (DENC + HH)];             // interleaved [W_ih0[:,E:] | W_hh0]
__device__ float g_Wc1[G4H * (HH + HH)];               // interleaved [W_ih1 | W_hh1]
__device__ float g_Wemb0[G4H * EE];                    // interleaved W_ih0[:, :E]
__device__ float g_token_gates[VV * G4H];              // per-token gates add (interleaved)
__device__ float g_token_preds[VV * VV];               // per-token W_out emb part + b_out
__device__ int   g_tokens[BB * TT];                    // input token per (b,t)
__device__ float g_xbuf[2][BB * (DENC + HH)];          // [context | h0], ping-pong
__device__ float g_x1buf[2][BB * (HH + HH)];           // [h0n | h1], ping-pong
__device__ float g_c0buf[BB * HH];
__device__ float g_c1buf[BB * HH];
__device__ float g_decproj[BB * HH];

__device__ __forceinline__ float sigmoid_fast(float x) {
    return __fdividef(1.0f, 1.0f + __expf(-x));
}
__device__ __forceinline__ float tanh_hw(float x) {
    float y;
    asm("tanh.approx.f32 %0, %1;" : "=f"(y) : "f"(x));
    return y;
}

__device__ __forceinline__ uint32_t f2tf32(float x) {
    uint32_t r;
    asm("cvt.rna.tf32.f32 %0, %1;" : "=r"(r) : "f"(x));
    return r;
}

__device__ __forceinline__ void mma_tf32(float* c, const uint32_t* a, const uint32_t* b) {
    asm volatile(
        "mma.sync.aligned.m16n8k8.row.col.f32.tf32.tf32.f32 "
        "{%0,%1,%2,%3},{%4,%5,%6,%7},{%8,%9},{%0,%1,%2,%3};"
        : "+f"(c[0]), "+f"(c[1]), "+f"(c[2]), "+f"(c[3])
        : "r"(a[0]), "r"(a[1]), "r"(a[2]), "r"(a[3]), "r"(b[0]), "r"(b[1]));
}

// ---------------- TF32 tensor-core NT GEMM (R7 layout), optional fused LSTM ----------------
// C[M,N] = A(MxK) * B(NxK)^T
// rowtok: Cin row index = rowtok[row*rts] (token-indexed Cin gather), else row.
// LSTM=1: gate-interleaved columns (col = 4h+gate, order i,f,g,o); epilogue stages the
// tile to padded smem then computes the cell with coalesced global I/O.
template <int BM, int BN, int BK, int WM, int WN, int LSTM>
__global__ void __launch_bounds__((BM / WM) * (BN / WN) * 32, 2)
mma_nt_kernel(int M, int N, int K,
              const float* __restrict__ A, int lda,
              const float* __restrict__ B, int ldb,
              void* __restrict__ Cv, int ldc,
              const float* __restrict__ Cin, int ldcin,
              const float* __restrict__ bias0,
              const float* __restrict__ bias1,
              const int* __restrict__ rowtok, int rts,
              int accumulate, int out_bf16,
              float* __restrict__ cbuf,
              float* __restrict__ hA, int ldA,
              float* __restrict__ hB, int ldB) {
    constexpr int WARPS_M = BM / WM, WARPS_N = BN / WN;
    constexpr int NW = WARPS_M * WARPS_N, THREADS = NW * 32;
    constexpr int MI = WM / 16, NI = WN / 8, KI = BK / 8;
    constexpr int PAD = 8;
    constexpr int A_LD4 = BM * (BK / 4) / THREADS;
    constexpr int B_LD4 = BN * (BK / 4) / THREADS;

    constexpr int STAGE_WORDS = 2 * BK * (BM + PAD) + 2 * BK * (BN + PAD);
    constexpr int CS_LD = BN + 4;
    constexpr int CS_WORDS = LSTM ? BM * CS_LD : 0;
    constexpr int SMEM_WORDS = STAGE_WORDS > CS_WORDS ? STAGE_WORDS : CS_WORDS;

    __shared__ __align__(16) uint32_t sm[SMEM_WORDS];
    uint32_t* Asb = sm;
    uint32_t* Bsb = sm + 2 * BK * (BM + PAD);
#define AS_(b, k, m) Asb[((b) * BK + (k)) * (BM + PAD) + (m)]
#define BS_(b, k, n) Bsb[((b) * BK + (k)) * (BN + PAD) + (n)]

    const int tid = threadIdx.x;
    const int wid = tid >> 5, lane = tid & 31;
    const int wm = (wid / WARPS_N) * WM, wn = (wid % WARPS_N) * WN;
    const int g = lane >> 2, tg = lane & 3;
    const int bm = blockIdx.y * BM, bn = blockIdx.x * BN;

    float acc[MI][NI][4];
#pragma unroll
    for (int i = 0; i < MI; i++)
#pragma unroll
        for (int j = 0; j < NI; j++)
#pragma unroll
            for (int q = 0; q < 4; q++) acc[i][j][q] = 0.0f;

    float4 ra[A_LD4], rb[B_LD4];

    auto load_tile = [&](int k0) {
#pragma unroll
        for (int i = 0; i < A_LD4; i++) {
            int idx = tid + i * THREADS;
            int m = idx / (BK / 4), kq = (idx % (BK / 4)) * 4;
            ra[i] = *(const float4*)(A + (size_t)(bm + m) * lda + k0 + kq);
        }
#pragma unroll
        for (int i = 0; i < B_LD4; i++) {
            int idx = tid + i * THREADS;
            int n = idx / (BK / 4), kq = (idx % (BK / 4)) * 4;
            rb[i] = *(const float4*)(B + (size_t)(bn + n) * ldb + k0 + kq);
        }
    };
    auto store_tile = [&](int buf) {
#pragma unroll
        for (int i = 0; i < A_LD4; i++) {
            int idx = tid + i * THREADS;
            int m = idx / (BK / 4), kq = (idx % (BK / 4)) * 4;
            AS_(buf, kq + 0, m) = f2tf32(ra[i].x);
            AS_(buf, kq + 1, m) = f2tf32(ra[i].y);
            AS_(buf, kq + 2, m) = f2tf32(ra[i].z);
            AS_(buf, kq + 3, m) = f2tf32(ra[i].w);
        }
#pragma unroll
        for (int i = 0; i < B_LD4; i++) {
            int idx = tid + i * THREADS;
            int n = idx / (BK / 4), kq = (idx % (BK / 4)) * 4;
            BS_(buf, kq + 0, n) = f2tf32(rb[i].x);
            BS_(buf, kq + 1, n) = f2tf32(rb[i].y);
            BS_(buf, kq + 2, n) = f2tf32(rb[i].z);
            BS_(buf, kq + 3, n) = f2tf32(rb[i].w);
        }
    };

    load_tile(0);
    store_tile(0);
    __syncthreads();

    int buf = 0;
    for (int k0 = 0; k0 < K; k0 += BK) {
        const bool has_next = (k0 + BK) < K;
        if (has_next) load_tile(k0 + BK);

#pragma unroll
        for (int ki = 0; ki < KI; ki++) {
            uint32_t af[MI][4];
            uint32_t bfv[NI][2];
#pragma unroll
            for (int mi = 0; mi < MI; mi++) {
                int mrow = wm + mi * 16 + g;
                af[mi][0] = AS_(buf, ki * 8 + tg, mrow);
                af[mi][1] = AS_(buf, ki * 8 + tg, mrow + 8);
                af[mi][2] = AS_(buf, ki * 8 + tg + 4, mrow);
                af[mi][3] = AS_(buf, ki * 8 + tg + 4, mrow + 8);
            }
#pragma unroll
            for (int ni = 0; ni < NI; ni++) {
                int ncol = wn + ni * 8 + g;
                bfv[ni][0] = BS_(buf, ki * 8 + tg, ncol);
                bfv[ni][1] = BS_(buf, ki * 8 + tg + 4, ncol);
            }
#pragma unroll
            for (int mi = 0; mi < MI; mi++)
#pragma unroll
                for (int ni = 0; ni < NI; ni++) mma_tf32(acc[mi][ni], af[mi], bfv[ni]);
        }

        if (has_next) store_tile(buf ^ 1);
        __syncthreads();
        buf ^= 1;
    }

    if (LSTM) {
        // phase 1: stage acc tile into padded smem (conflict-free float2 stores)
        float* Cs = (float*)sm;
#pragma unroll
        for (int mi = 0; mi < MI; mi++) {
#pragma unroll
            for (int ni = 0; ni < NI; ni++) {
                const int lr = wm + mi * 16 + g;
                const int lc = wn + ni * 8 + tg * 2;
                *(float2*)&Cs[lr * CS_LD + lc] = make_float2(acc[mi][ni][0], acc[mi][ni][1]);
                *(float2*)&Cs[(lr + 8) * CS_LD + lc] = make_float2(acc[mi][ni][2], acc[mi][ni][3]);
            }
        }
        __syncthreads();

        // phase 2: lane = local h (32 per BN=128 tile); coalesced global I/O
        const int h_l = lane;
        const int h_g = (bn >> 2) + h_l;
        const float bi = bias0[0 * HH + h_g] + bias1[0 * HH + h_g];
        const float bff = bias0[1 * HH + h_g] + bias1[1 * HH + h_g];
        const float bg = bias0[2 * HH + h_g] + bias1[2 * HH + h_g];
        const float bo = bias0[3 * HH + h_g] + bias1[3 * HH + h_g];
        for (int rr = wid; rr < BM; rr += NW) {
            const int row = bm + rr;
            float4 gv = *(const float4*)&Cs[rr * CS_LD + 4 * h_l];
            float gi = gv.x + bi, gf = gv.y + bff, gg = gv.z + bg, go = gv.w + bo;
            if (Cin) {
                const int crow = rowtok ? rowtok[row * rts] : row;
                float4 ci = *(const float4*)(Cin + (size_t)crow * ldcin + bn + 4 * h_l);
                gi += ci.x; gf += ci.y; gg += ci.z; go += ci.w;
            }
            float cn = sigmoid_fast(gf) * cbuf[(size_t)row * HH + h_g] +
                       sigmoid_fast(gi) * tanhf(gg);
            cbuf[(size_t)row * HH + h_g] = cn;
            float hn = sigmoid_fast(go) * tanhf(cn);
            hA[(size_t)row * ldA + h_g] = hn;
            hB[(size_t)row * ldB + h_g] = hn;
        }
        return;
    }

    // normal epilogue
#pragma unroll
    for (int mi = 0; mi < MI; mi++) {
#pragma unroll
        for (int ni = 0; ni < NI; ni++) {
            const int col = bn + wn + ni * 8 + tg * 2;
#pragma unroll
            for (int half = 0; half < 2; half++) {
                const int row = bm + wm + mi * 16 + g + half * 8;
                float v0 = acc[mi][ni][half * 2 + 0];
                float v1 = acc[mi][ni][half * 2 + 1];
                if (out_bf16) {
                    __nv_bfloat162* cp =
                        (__nv_bfloat162*)((__nv_bfloat16*)Cv + (size_t)row * ldc + col);
                    *cp = __float22bfloat162_rn(make_float2(v0, v1));
                    continue;
                }
                float* C = (float*)Cv;
                if (bias0) { v0 += bias0[col]; v1 += bias0[col + 1]; }
                if (bias1) { v0 += bias1[col]; v1 += bias1[col + 1]; }
                if (Cin) {
                    const int crow = rowtok ? rowtok[row * rts] : row;
                    float2 ci = *(const float2*)(Cin + (size_t)crow * ldcin + col);
                    v0 += ci.x; v1 += ci.y;
                }
                float2* cp = (float2*)(C + (size_t)row * ldc + col);
                if (accumulate) {
                    float2 c = *cp;
                    v0 += c.x; v1 += c.y;
                }
                *cp = make_float2(v0, v1);
            }
        }
    }
#undef AS_
#undef BS_
}

template <int BM, int BN, int BK, int WM, int WN>
static void mgemm(int M, int N, int K,
                  const float* A, int lda, const float* B, int ldb,
                  void* C, int ldc,
                  const float* Cin = nullptr, int ldcin = 0,
                  const float* bias0 = nullptr, const float* bias1 = nullptr,
                  const int* rowtok = nullptr, int rts = 1,
                  bool accumulate = false, bool out_bf16 = false) {
    dim3 grid(N / BN, M / BM);
    mma_nt_kernel<BM, BN, BK, WM, WN, 0><<<grid, (BM / WM) * (BN / WN) * 32>>>(
        M, N, K, A, lda, B, ldb, C, ldc, Cin, ldcin, bias0, bias1, rowtok, rts,
        accumulate ? 1 : 0, out_bf16 ? 1 : 0, nullptr, nullptr, 0, nullptr, 0);
}

template <int BM, int BN, int BK, int WM, int WN>
static void mgemm_lstm(int M, int N, int K,
                       const float* A, int lda, const float* B, int ldb,
                       const float* Cin, int ldcin,
                       const float* b_ih, const float* b_hh,
                       const int* rowtok, int rts,
                       float* cbuf, float* hA, int ldA, float* hB, int ldB) {
    dim3 grid(N / BN, M / BM);
    mma_nt_kernel<BM, BN, BK, WM, WN, 1><<<grid, (BM / WM) * (BN / WN) * 32>>>(
        M, N, K, A, lda, B, ldb, nullptr, 0, Cin, ldcin, b_ih, b_hh, rowtok, rts,
        0, 0, cbuf, hA, ldA, hB, ldB);
}

// ---------------- precompute kernels ----------------
__global__ void tokens_kernel(const int* __restrict__ targets, int* __restrict__ toks) {
    int idx = blockIdx.x * blockDim.x + threadIdx.x;  // B*T
    int t = idx & (TT - 1);
    int b = idx >> 5;
    toks[idx] = (t == 0) ? EOS_IDX : targets[b * TT + t - 1];
}

// gate-interleaved combined weights (col n' = 4h + gate; orig row = gate*H + h)
__global__ void build_wcomb_kernel(const float* __restrict__ W_ih0,
                                   const float* __restrict__ W_hh0,
                                   const float* __restrict__ W_ih1,
                                   const float* __restrict__ W_hh1,
                                   float* __restrict__ Wc0,
                                   float* __restrict__ Wc1,
                                   float* __restrict__ Wemb0) {
    int idx = blockIdx.x * blockDim.x + threadIdx.x;
    const int N0 = G4H * (DENC + HH);
    const int N1 = G4H * (HH + HH);
    const int N2 = G4H * EE;
    if (idx < N0) {
        int np = idx / (DENC + HH);
        int k = idx % (DENC + HH);
        int orig = (np & 3) * HH + (np >> 2);
        Wc0[idx] = (k < DENC) ? W_ih0[(size_t)orig * (EE + DENC) + EE + k]
                              : W_hh0[(size_t)orig * HH + (k - DENC)];
    } else if (idx < N0 + N1) {
        int r = idx - N0;
        int np = r / (HH + HH);
        int k = r % (HH + HH);
        int orig = (np & 3) * HH + (np >> 2);
        Wc1[r] = (k < HH) ? W_ih1[(size_t)orig * HH + k]
                          : W_hh1[(size_t)orig * HH + (k - HH)];
    } else if (idx < N0 + N1 + N2) {
        int r = idx - N0 - N1;
        int np = r / EE;
        int e = r % EE;
        int orig = (np & 3) * HH + (np >> 2);
        Wemb0[r] = W_ih0[(size_t)orig * (EE + DENC) + e];
    }
}

__global__ void init_state_kernel(const float* __restrict__ h0,
                                  const float* __restrict__ c0,
                                  float* __restrict__ xbuf0,
                                  float* __restrict__ x1buf0,
                                  float* __restrict__ cb0,
                                  float* __restrict__ cb1) {
    int idx = blockIdx.x * blockDim.x + threadIdx.x;  // B*H
    int b = idx >> 9;
    int h = idx & (HH - 1);
    xbuf0[(size_t)b * (DENC + HH) + DENC + h] = h0[idx];
    x1buf0[(size_t)b * (HH + HH) + HH + h] = h0[(size_t)BB * HH + idx];
    cb0[idx] = c0[idx];
    cb1[idx] = c0[(size_t)BB * HH + idx];
}

// ---------------- attention (fused score/tanh + masked softmax + context) ----------------
__global__ void __launch_bounds__(256) attention_kernel(
    const __nv_bfloat16* __restrict__ enc_proj,   // (B,S,H) bf16
    const float* __restrict__ enc,        // (B,S,DENC) fp32
    const float* __restrict__ decp,       // (B,H)
    const float* __restrict__ vvec,       // (H)
    const int* __restrict__ mask,         // (B,S)
    float* __restrict__ ctx_dst1, int ld1,
    float* __restrict__ ctx_dst2, int ld2) {
    const int b = blockIdx.x;
    __shared__ float s_dp[HH];
    __shared__ float s_v[HH];
    __shared__ float s_w[SS];
    __shared__ float s_red[2];
    const int tid = threadIdx.x;
    const int warp = tid >> 5, lane = tid & 31;

    for (int i = tid; i < HH; i += 256) {
        s_dp[i] = decp[(size_t)b * HH + i];
        s_v[i] = vvec[i];
    }
    __syncthreads();

    for (int s = warp; s < SS; s += 8) {
        const __nv_bfloat162* ep =
            (const __nv_bfloat162*)(enc_proj + ((size_t)b * SS + s) * HH);
        float acc = 0.0f;
#pragma unroll 4
        for (int h2 = lane; h2 < HH / 2; h2 += 32) {
            float2 e = __bfloat1622float2(ep[h2]);
            acc += s_v[2 * h2] * tanh_hw(s_dp[2 * h2] + e.x);
            acc += s_v[2 * h2 + 1] * tanh_hw(s_dp[2 * h2 + 1] + e.y);
        }
#pragma unroll
        for (int o = 16; o; o >>= 1) acc += __shfl_xor_sync(0xffffffffu, acc, o);
        if (lane == 0) s_w[s] = mask[b * SS + s] ? acc : -1e30f;
    }
    __syncthreads();

    if (warp == 0) {
        float m = fmaxf(s_w[lane], s_w[lane + 32]);
#pragma unroll
        for (int o = 16; o; o >>= 1) m = fmaxf(m, __shfl_xor_sync(0xffffffffu, m, o));
        float sum = __expf(s_w[lane] - m) + __expf(s_w[lane + 32] - m);
#pragma unroll
        for (int o = 16; o; o >>= 1) sum += __shfl_xor_sync(0xffffffffu, sum, o);
        if (lane == 0) { s_red[0] = m; s_red[1] = sum; }
    }
    __syncthreads();
    const float m = s_red[0], inv = 1.0f / s_red[1];
    if (tid < SS) s_w[tid] = __expf(s_w[tid] - m) * inv;
    __syncthreads();

    const float* eb = enc + (size_t)b * SS * DENC;
    for (int d = tid; d < DENC; d += 256) {
        float acc = 0.0f;
#pragma unroll 8
        for (int s = 0; s < SS; s++) acc += s_w[s] * eb[(size_t)s * DENC + d];
        ctx_dst1[(size_t)b * ld1 + d] = acc;
        ctx_dst2[(size_t)b * ld2 + d] = acc;
    }
}

// ---------------- host ----------------
extern "C" void kernel_launch(void* const* d_in, const int* in_sizes, int n_in,
                              void* d_out, int out_size) {
    const float* encoder_out = (const float*)d_in[0];
    const float* h0   = (const float*)d_in[1];
    const float* c0   = (const float*)d_in[2];
    const int*   targets = (const int*)d_in[3];
    const int*   mask    = (const int*)d_in[4];
    const float* emb   = (const float*)d_in[5];
    const float* W_enc = (const float*)d_in[6];
    const float* W_dec = (const float*)d_in[7];
    const float* vvec  = (const float*)d_in[8];
    const float* W_ih0 = (const float*)d_in[9];
    const float* W_hh0 = (const float*)d_in[10];
    const float* b_ih0 = (const float*)d_in[11];
    const float* b_hh0 = (const float*)d_in[12];
    const float* W_ih1 = (const float*)d_in[13];
    const float* W_hh1 = (const float*)d_in[14];
    const float* b_ih1 = (const float*)d_in[15];
    const float* b_hh1 = (const float*)d_in[16];
    const float* W_out = (const float*)d_in[17];
    const float* b_out = (const float*)d_in[18];
    float* out = (float*)d_out;  // (B,T,V)

    __nv_bfloat16* p_encproj_bf;
    float *p_pred, *p_Wc0, *p_Wc1, *p_Wemb0, *p_tokg, *p_tokp;
    float *p_xbuf, *p_x1buf, *p_c0, *p_c1, *p_decproj;
    int* p_tokens;
    cudaGetSymbolAddress((void**)&p_encproj_bf, g_encproj_bf);
    cudaGetSymbolAddress((void**)&p_pred, g_pred);
    cudaGetSymbolAddress((void**)&p_Wc0, g_Wc0);
    cudaGetSymbolAddress((void**)&p_Wc1, g_Wc1);
    cudaGetSymbolAddress((void**)&p_Wemb0, g_Wemb0);
    cudaGetSymbolAddress((void**)&p_tokg, g_token_gates);
    cudaGetSymbolAddress((void**)&p_tokp, g_token_preds);
    cudaGetSymbolAddress((void**)&p_tokens, g_tokens);
    cudaGetSymbolAddress((void**)&p_xbuf, g_xbuf);
    cudaGetSymbolAddress((void**)&p_x1buf, g_x1buf);
    cudaGetSymbolAddress((void**)&p_c0, g_c0buf);
    cudaGetSymbolAddress((void**)&p_c1, g_c1buf);
    cudaGetSymbolAddress((void**)&p_decproj, g_decproj);

    float* xb[2] = {p_xbuf, p_xbuf + (size_t)BB * (DENC + HH)};
    float* x1[2] = {p_x1buf, p_x1buf + (size_t)BB * (HH + HH)};

    // ---- precompute ----
    tokens_kernel<<<(BB * TT) / 256, 256>>>(targets, p_tokens);
    {
        int total = G4H * (DENC + HH) + G4H * (HH + HH) + G4H * EE;
        build_wcomb_kernel<<<(total + 255) / 256, 256>>>(W_ih0, W_hh0, W_ih1, W_hh1,
                                                         p_Wc0, p_Wc1, p_Wemb0);
    }
    init_state_kernel<<<(BB * HH) / 256, 256>>>(h0, c0, xb[0], x1[0], p_c0, p_c1);

    // token_gates (V,4H interleaved) = emb @ Wemb0^T
    mgemm<64, 128, 16, 32, 64>(VV, G4H, EE, emb, EE, p_Wemb0, EE, p_tokg, G4H);
    // token_preds (V,V) = emb @ W_out[:, H+DENC:]^T + b_out
    mgemm<64, 64, 16, 32, 32>(VV, VV, EE, emb, EE, W_out + (HH + DENC), HH + DENC + EE,
                              p_tokp, VV, nullptr, 0, b_out);
    // enc_proj -> bf16 (score path only)
    mgemm<128, 128, 16, 64, 32>(BB * SS, HH, DENC, encoder_out, DENC, W_enc, DENC,
                                p_encproj_bf, HH, nullptr, 0, nullptr, nullptr,
                                nullptr, 1, false, true);

    // ---- sequential decode ----
    for (int t = 0; t < TT; t++) {
        const int r = t & 1, w = r ^ 1;

        // dec_proj = h1 @ W_dec^T
        mgemm<64, 64, 16, 32, 32>(BB, HH, HH, x1[r] + HH, HH + HH, W_dec, HH,
                                  p_decproj, HH);

        // attention: context -> xbuf[r][:, :DENC] and pred[:, t, H:]
        attention_kernel<<<BB, 256>>>(p_encproj_bf, encoder_out, p_decproj, vvec, mask,
                                      xb[r], DENC + HH,
                                      p_pred + (size_t)t * PCOL + HH, TT * PCOL);

        // layer-0 fused: gates + cell; h0n -> x1[r][:, :H] and xbuf[w][:, DENC:]
        mgemm_lstm<64, 128, 16, 32, 64>(BB, G4H, DENC + HH,
                                        xb[r], DENC + HH, p_Wc0, DENC + HH,
                                        p_tokg, G4H, b_ih0, b_hh0,
                                        p_tokens + t, TT,
                                        p_c0, x1[r], HH + HH, xb[w] + DENC, DENC + HH);

        // layer-1 fused: gates + cell; h1n -> x1[w][:, H:] and pred[:, t, :H]
        mgemm_lstm<64, 128, 16, 32, 64>(BB, G4H, HH + HH,
                                        x1[r], HH + HH, p_Wc1, HH + HH,
                                        nullptr, 0, b_ih1, b_hh1,
                                        nullptr, 1,
                                        p_c1, x1[w] + HH, HH + HH,
                                        p_pred + (size_t)t * PCOL, TT * PCOL);
    }

    // logits: out = [h1n|context] @ W_out[:, :H+DENC]^T + token_preds[tok(b,t)]
    mgemm<128, 128, 16, 64, 32>(BB * TT, VV, PCOL, p_pred, PCOL, W_out, HH + DENC + EE,
                                out, VV, p_tokp, VV, nullptr, nullptr,
                                p_tokens, 1);
}

// round 10
// speedup vs baseline: 1.2981x; 1.2981x over previous
#include <cuda_runtime.h>
#include <cuda_bf16.h>
#include <math.h>
#include <stdint.h>

#define BB 512
#define SS 64
#define TT 32
#define VV 128
#define EE 256
#define HH 512
#define DENC 1024
#define G4H 2048
#define EOS_IDX 2
#define PCOL (HH + DENC)  /* 1536 */

// ---------------- scratch (device globals; no allocations) ----------------
__device__ __nv_bfloat16 g_encproj_bf[(size_t)BB * SS * HH];  // 32 MB (score path)
__device__ float g_pred[(size_t)BB * TT * PCOL];       // 100 MB  [h1n | context]
__device__ float g_Wc0[G4H * (DENC + HH)];             // [W_ih0[:,E:] | W_hh0]
__device__ float g_Wc1[G4H * (HH + HH)];               // [W_ih1 | W_hh1]
__device__ float g_token_gates[VV * G4H];              // per-token W_ih0[:, :E] @ emb
__device__ float g_token_preds[VV * VV];               // per-token W_out emb part + b_out
__device__ int   g_tokens[BB * TT];                    // input token per (b,t)
__device__ float g_xbuf[BB * (DENC + HH)];             // [context | h0]
__device__ float g_x1buf[BB * (HH + HH)];              // [h0n | h1]
__device__ float g_gates[BB * G4H];
__device__ float g_c0buf[BB * HH];
__device__ float g_c1buf[BB * HH];
__device__ float g_decproj[BB * HH];

__device__ __forceinline__ float sigmoid_fast(float x) {
    return __fdividef(1.0f, 1.0f + __expf(-x));
}
__device__ __forceinline__ float tanh_hw(float x) {
    float y;
    asm("tanh.approx.f32 %0, %1;" : "=f"(y) : "f"(x));
    return y;
}

__device__ __forceinline__ uint32_t f2tf32(float x) {
    uint32_t r;
    asm("cvt.rna.tf32.f32 %0, %1;" : "=r"(r) : "f"(x));
    return r;
}

__device__ __forceinline__ uint32_t smem_u32(const void* p) {
    return (uint32_t)__cvta_generic_to_shared(p);
}
__device__ __forceinline__ void cp_async16(void* smem, const void* gmem) {
    asm volatile("cp.async.cg.shared.global [%0], [%1], 16;"
                 :: "r"(smem_u32(smem)), "l"(gmem));
}
__device__ __forceinline__ void cp_commit() {
    asm volatile("cp.async.commit_group;");
}
template <int N>
__device__ __forceinline__ void cp_wait() {
    asm volatile("cp.async.wait_group %0;" :: "n"(N));
}

__device__ __forceinline__ void mma_tf32(float* c, const uint32_t* a, const uint32_t* b) {
    asm volatile(
        "mma.sync.aligned.m16n8k8.row.col.f32.tf32.tf32.f32 "
        "{%0,%1,%2,%3},{%4,%5,%6,%7},{%8,%9},{%0,%1,%2,%3};"
        : "+f"(c[0]), "+f"(c[1]), "+f"(c[2]), "+f"(c[3])
        : "r"(a[0]), "r"(a[1]), "r"(a[2]), "r"(a[3]), "r"(b[0]), "r"(b[1]));
}

// ---------------- TF32 tensor-core NT GEMM, 3-stage cp.async pipeline ----------------
// C[M,N] = A(MxK) * B(NxK)^T  (+bias0[n]+bias1[n]+Cin[row', n]; optional += C; bf16 out)
// rowtok: if non-null, Cin row index = rowtok[row * rts].
// smem holds raw fp32, row-major [row][BK+4]; cvt to tf32 at fragment load (rna).
template <int BM, int BN, int BK, int WM, int WN>
__global__ void __launch_bounds__((BM / WM) * (BN / WN) * 32,
                                  512 / ((BM / WM) * (BN / WN) * 32))
mma_nt_kernel(int M, int N, int K,
              const float* __restrict__ A, int lda,
              const float* __restrict__ B, int ldb,
              void* __restrict__ Cv, int ldc,
              const float* __restrict__ Cin, int ldcin,
              const float* __restrict__ bias0,
              const float* __restrict__ bias1,
              const int* __restrict__ rowtok, int rts,
              int accumulate, int out_bf16) {
    constexpr int WARPS_M = BM / WM, WARPS_N = BN / WN;
    constexpr int NW = WARPS_M * WARPS_N, THREADS = NW * 32;
    constexpr int MI = WM / 16, NI = WN / 8, KI = BK / 8;
    constexpr int LDS_ = BK + 4;                 // stride 20 words: conflict-free
    constexpr int STAGES = 3;
    constexpr int A_CP = BM * (BK / 4) / THREADS;  // 16B copies per thread (A)
    constexpr int B_CP = BN * (BK / 4) / THREADS;  // 16B copies per thread (B)

    __shared__ __align__(16) float As[STAGES][BM][LDS_];
    __shared__ __align__(16) float Bs[STAGES][BN][LDS_];

    const int tid = threadIdx.x;
    const int wid = tid >> 5, lane = tid & 31;
    const int wm = (wid / WARPS_N) * WM, wn = (wid % WARPS_N) * WN;
    const int g = lane >> 2, tg = lane & 3;
    const int bm = blockIdx.y * BM, bn = blockIdx.x * BN;

    float acc[MI][NI][4];
#pragma unroll
    for (int i = 0; i < MI; i++)
#pragma unroll
        for (int j = 0; j < NI; j++)
#pragma unroll
            for (int q = 0; q < 4; q++) acc[i][j][q] = 0.0f;

    auto issue_tile = [&](int tile, int slot) {
        const int k0 = tile * BK;
#pragma unroll
        for (int i = 0; i < A_CP; i++) {
            int idx = tid + i * THREADS;
            int m = idx / (BK / 4), kq = (idx % (BK / 4)) * 4;
            cp_async16(&As[slot][m][kq], A + (size_t)(bm + m) * lda + k0 + kq);
        }
#pragma unroll
        for (int i = 0; i < B_CP; i++) {
            int idx = tid + i * THREADS;
            int n = idx / (BK / 4), kq = (idx % (BK / 4)) * 4;
            cp_async16(&Bs[slot][n][kq], B + (size_t)(bn + n) * ldb + k0 + kq);
        }
    };

    const int ntiles = K / BK;
    issue_tile(0, 0);
    cp_commit();
    if (ntiles > 1) issue_tile(1, 1);
    cp_commit();

    for (int t = 0; t < ntiles; t++) {
        cp_wait<1>();
        __syncthreads();
        const int slot = t % STAGES;

#pragma unroll
        for (int ki = 0; ki < KI; ki++) {
            const int k_lo = ki * 8 + tg, k_hi = k_lo + 4;
            uint32_t af[MI][4];
            uint32_t bfv[NI][2];
#pragma unroll
            for (int mi = 0; mi < MI; mi++) {
                const int mr = wm + mi * 16 + g;
                af[mi][0] = f2tf32(As[slot][mr][k_lo]);
                af[mi][1] = f2tf32(As[slot][mr + 8][k_lo]);
                af[mi][2] = f2tf32(As[slot][mr][k_hi]);
                af[mi][3] = f2tf32(As[slot][mr + 8][k_hi]);
            }
#pragma unroll
            for (int ni = 0; ni < NI; ni++) {
                const int nr = wn + ni * 8 + g;
                bfv[ni][0] = f2tf32(Bs[slot][nr][k_lo]);
                bfv[ni][1] = f2tf32(Bs[slot][nr][k_hi]);
            }
#pragma unroll
            for (int mi = 0; mi < MI; mi++)
#pragma unroll
                for (int ni = 0; ni < NI; ni++) mma_tf32(acc[mi][ni], af[mi], bfv[ni]);
        }

        __syncthreads();  // all reads of slot (t-? ) done before refill below
        if (t + 2 < ntiles) issue_tile(t + 2, (t + 2) % STAGES);
        cp_commit();
    }

    // epilogue
#pragma unroll
    for (int mi = 0; mi < MI; mi++) {
#pragma unroll
        for (int ni = 0; ni < NI; ni++) {
            const int col = bn + wn + ni * 8 + tg * 2;
#pragma unroll
            for (int half = 0; half < 2; half++) {
                const int row = bm + wm + mi * 16 + g + half * 8;
                float v0 = acc[mi][ni][half * 2 + 0];
                float v1 = acc[mi][ni][half * 2 + 1];
                if (out_bf16) {
                    __nv_bfloat162* cp =
                        (__nv_bfloat162*)((__nv_bfloat16*)Cv + (size_t)row * ldc + col);
                    *cp = __float22bfloat162_rn(make_float2(v0, v1));
                    continue;
                }
                float* C = (float*)Cv;
                if (bias0) { v0 += bias0[col]; v1 += bias0[col + 1]; }
                if (bias1) { v0 += bias1[col]; v1 += bias1[col + 1]; }
                if (Cin) {
                    const int crow = rowtok ? rowtok[row * rts] : row;
                    float2 ci = *(const float2*)(Cin + (size_t)crow * ldcin + col);
                    v0 += ci.x; v1 += ci.y;
                }
                float2* cp = (float2*)(C + (size_t)row * ldc + col);
                if (accumulate) {
                    float2 c = *cp;
                    v0 += c.x; v1 += c.y;
                }
                *cp = make_float2(v0, v1);
            }
        }
    }
}

template <int BM, int BN, int BK, int WM, int WN>
static void mgemm(int M, int N, int K,
                  const float* A, int lda, const float* B, int ldb,
                  void* C, int ldc,
                  const float* Cin = nullptr, int ldcin = 0,
                  const float* bias0 = nullptr, const float* bias1 = nullptr,
                  const int* rowtok = nullptr, int rts = 1,
                  bool accumulate = false, bool out_bf16 = false) {
    dim3 grid(N / BN, M / BM);
    mma_nt_kernel<BM, BN, BK, WM, WN><<<grid, (BM / WM) * (BN / WN) * 32>>>(
        M, N, K, A, lda, B, ldb, C, ldc, Cin, ldcin, bias0, bias1, rowtok, rts,
        accumulate ? 1 : 0, out_bf16 ? 1 : 0);
}

// ---------------- precompute kernels ----------------
__global__ void tokens_kernel(const int* __restrict__ targets, int* __restrict__ toks) {
    int idx = blockIdx.x * blockDim.x + threadIdx.x;  // B*T
    int t = idx & (TT - 1);
    int b = idx >> 5;
    toks[idx] = (t == 0) ? EOS_IDX : targets[b * TT + t - 1];
}

// plain-layout combined weights
__global__ void build_wcomb_kernel(const float* __restrict__ W_ih0,
                                   const float* __restrict__ W_hh0,
                                   const float* __restrict__ W_ih1,
                                   const float* __restrict__ W_hh1,
                                   float* __restrict__ Wc0,
                                   float* __restrict__ Wc1) {
    int idx = blockIdx.x * blockDim.x + threadIdx.x;
    const int N0 = G4H * (DENC + HH);
    const int N1 = G4H * (HH + HH);
    if (idx < N0) {
        int n = idx / (DENC + HH);
        int k = idx % (DENC + HH);
        Wc0[idx] = (k < DENC) ? W_ih0[(size_t)n * (EE + DENC) + EE + k]
                              : W_hh0[(size_t)n * HH + (k - DENC)];
    } else if (idx < N0 + N1) {
        int r = idx - N0;
        int n = r / (HH + HH);
        int k = r % (HH + HH);
        Wc1[r] = (k < HH) ? W_ih1[(size_t)n * HH + k]
                          : W_hh1[(size_t)n * HH + (k - HH)];
    }
}

__global__ void init_state_kernel(const float* __restrict__ h0,
                                  const float* __restrict__ c0,
                                  float* __restrict__ xbuf,
                                  float* __restrict__ x1buf,
                                  float* __restrict__ cb0,
                                  float* __restrict__ cb1) {
    int idx = blockIdx.x * blockDim.x + threadIdx.x;  // B*H
    int b = idx >> 9;
    int h = idx & (HH - 1);
    xbuf[(size_t)b * (DENC + HH) + DENC + h] = h0[idx];
    x1buf[(size_t)b * (HH + HH) + HH + h] = h0[(size_t)BB * HH + idx];
    cb0[idx] = c0[idx];
    cb1[idx] = c0[(size_t)BB * HH + idx];
}

// ---------------- attention (fused score/tanh + masked softmax + context) ----------------
__global__ void __launch_bounds__(256) attention_kernel(
    const __nv_bfloat16* __restrict__ enc_proj,   // (B,S,H) bf16
    const float* __restrict__ enc,        // (B,S,DENC) fp32
    const float* __restrict__ decp,       // (B,H)
    const float* __restrict__ vvec,       // (H)
    const int* __restrict__ mask,         // (B,S)
    float* __restrict__ ctx_dst1, int ld1,
    float* __restrict__ ctx_dst2, int ld2) {
    const int b = blockIdx.x;
    __shared__ float s_dp[HH];
    __shared__ float s_v[HH];
    __shared__ float s_w[SS];
    __shared__ float s_red[2];
    const int tid = threadIdx.x;
    const int warp = tid >> 5, lane = tid & 31;

    for (int i = tid; i < HH; i += 256) {
        s_dp[i] = decp[(size_t)b * HH + i];
        s_v[i] = vvec[i];
    }
    __syncthreads();

    for (int s = warp; s < SS; s += 8) {
        const __nv_bfloat162* ep =
            (const __nv_bfloat162*)(enc_proj + ((size_t)b * SS + s) * HH);
        float acc = 0.0f;
#pragma unroll 4
        for (int h2 = lane; h2 < HH / 2; h2 += 32) {
            float2 e = __bfloat1622float2(ep[h2]);
            acc += s_v[2 * h2] * tanh_hw(s_dp[2 * h2] + e.x);
            acc += s_v[2 * h2 + 1] * tanh_hw(s_dp[2 * h2 + 1] + e.y);
        }
#pragma unroll
        for (int o = 16; o; o >>= 1) acc += __shfl_xor_sync(0xffffffffu, acc, o);
        if (lane == 0) s_w[s] = mask[b * SS + s] ? acc : -1e30f;
    }
    __syncthreads();

    if (warp == 0) {
        float m = fmaxf(s_w[lane], s_w[lane + 32]);
#pragma unroll
        for (int o = 16; o; o >>= 1) m = fmaxf(m, __shfl_xor_sync(0xffffffffu, m, o));
        float sum = __expf(s_w[lane] - m) + __expf(s_w[lane + 32] - m);
#pragma unroll
        for (int o = 16; o; o >>= 1) sum += __shfl_xor_sync(0xffffffffu, sum, o);
        if (lane == 0) { s_red[0] = m; s_red[1] = sum; }
    }
    __syncthreads();
    const float m = s_red[0], inv = 1.0f / s_red[1];
    if (tid < SS) s_w[tid] = __expf(s_w[tid] - m) * inv;
    __syncthreads();

    // context: thread tid owns float4 d-chunk (DENC/4 == 256 == blockDim)
    const float4* eb4 = (const float4*)(enc + (size_t)b * SS * DENC);
    float4 acc4 = make_float4(0.f, 0.f, 0.f, 0.f);
#pragma unroll 8
    for (int s = 0; s < SS; s++) {
        const float w = s_w[s];
        float4 e = eb4[(size_t)s * (DENC / 4) + tid];
        acc4.x += w * e.x; acc4.y += w * e.y;
        acc4.z += w * e.z; acc4.w += w * e.w;
    }
    *(float4*)(ctx_dst1 + (size_t)b * ld1 + 4 * tid) = acc4;
    *(float4*)(ctx_dst2 + (size_t)b * ld2 + 4 * tid) = acc4;
}

// ---------------- LSTM pointwise cell (plain gate layout) ----------------
__global__ void lstm_cell_kernel(const float* __restrict__ gates,  // (B,4H)
                                 float* __restrict__ c,            // (B,H) in/out
                                 float* __restrict__ hA, int ldA,
                                 float* __restrict__ hB, int ldB) {
    int idx = blockIdx.x * blockDim.x + threadIdx.x;  // B*H
    int b = idx >> 9;
    int h = idx & (HH - 1);
    const float* g = gates + (size_t)b * G4H;
    float ig = sigmoid_fast(g[h]);
    float fg = sigmoid_fast(g[HH + h]);
    float gg = tanhf(g[2 * HH + h]);
    float og = sigmoid_fast(g[3 * HH + h]);
    float cn = fg * c[idx] + ig * gg;
    c[idx] = cn;
    float hn = og * tanhf(cn);
    hA[(size_t)b * ldA + h] = hn;
    hB[(size_t)b * ldB + h] = hn;
}

// ---------------- host ----------------
extern "C" void kernel_launch(void* const* d_in, const int* in_sizes, int n_in,
                              void* d_out, int out_size) {
    const float* encoder_out = (const float*)d_in[0];
    const float* h0   = (const float*)d_in[1];
    const float* c0   = (const float*)d_in[2];
    const int*   targets = (const int*)d_in[3];
    const int*   mask    = (const int*)d_in[4];
    const float* emb   = (const float*)d_in[5];
    const float* W_enc = (const float*)d_in[6];
    const float* W_dec = (const float*)d_in[7];
    const float* vvec  = (const float*)d_in[8];
    const float* W_ih0 = (const float*)d_in[9];
    const float* W_hh0 = (const float*)d_in[10];
    const float* b_ih0 = (const float*)d_in[11];
    const float* b_hh0 = (const float*)d_in[12];
    const float* W_ih1 = (const float*)d_in[13];
    const float* W_hh1 = (const float*)d_in[14];
    const float* b_ih1 = (const float*)d_in[15];
    const float* b_hh1 = (const float*)d_in[16];
    const float* W_out = (const float*)d_in[17];
    const float* b_out = (const float*)d_in[18];
    float* out = (float*)d_out;  // (B,T,V)

    __nv_bfloat16* p_encproj_bf;
    float *p_pred, *p_Wc0, *p_Wc1, *p_tokg, *p_tokp;
    float *p_xbuf, *p_x1buf, *p_gates, *p_c0, *p_c1, *p_decproj;
    int* p_tokens;
    cudaGetSymbolAddress((void**)&p_encproj_bf, g_encproj_bf);
    cudaGetSymbolAddress((void**)&p_pred, g_pred);
    cudaGetSymbolAddress((void**)&p_Wc0, g_Wc0);
    cudaGetSymbolAddress((void**)&p_Wc1, g_Wc1);
    cudaGetSymbolAddress((void**)&p_tokg, g_token_gates);
    cudaGetSymbolAddress((void**)&p_tokp, g_token_preds);
    cudaGetSymbolAddress((void**)&p_tokens, g_tokens);
    cudaGetSymbolAddress((void**)&p_xbuf, g_xbuf);
    cudaGetSymbolAddress((void**)&p_x1buf, g_x1buf);
    cudaGetSymbolAddress((void**)&p_gates, g_gates);
    cudaGetSymbolAddress((void**)&p_c0, g_c0buf);
    cudaGetSymbolAddress((void**)&p_c1, g_c1buf);
    cudaGetSymbolAddress((void**)&p_decproj, g_decproj);

    // ---- precompute ----
    tokens_kernel<<<(BB * TT) / 256, 256>>>(targets, p_tokens);
    {
        int total = G4H * (DENC + HH) + G4H * (HH + HH);
        build_wcomb_kernel<<<(total + 255) / 256, 256>>>(W_ih0, W_hh0, W_ih1, W_hh1,
                                                         p_Wc0, p_Wc1);
    }
    init_state_kernel<<<(BB * HH) / 256, 256>>>(h0, c0, p_xbuf, p_x1buf, p_c0, p_c1);

    // token_gates (V,4H) = emb @ W_ih0[:, :E]^T
    mgemm<64, 128, 16, 32, 64>(VV, G4H, EE, emb, EE, W_ih0, EE + DENC, p_tokg, G4H);
    // token_preds (V,V) = emb @ W_out[:, H+DENC:]^T + b_out
    mgemm<64, 64, 16, 32, 32>(VV, VV, EE, emb, EE, W_out + (HH + DENC), HH + DENC + EE,
                              p_tokp, VV, nullptr, 0, b_out);
    // enc_proj -> bf16 (score path only)
    mgemm<128, 128, 16, 64, 32>(BB * SS, HH, DENC, encoder_out, DENC, W_enc, DENC,
                                p_encproj_bf, HH, nullptr, 0, nullptr, nullptr,
                                nullptr, 1, false, true);

    // ---- sequential decode ----
    for (int t = 0; t < TT; t++) {
        // dec_proj = h1 @ W_dec^T
        mgemm<64, 64, 16, 32, 32>(BB, HH, HH, p_x1buf + HH, HH + HH, W_dec, HH,
                                  p_decproj, HH);

        // attention: context -> xbuf[:, :DENC] and pred[:, t, H:]
        attention_kernel<<<BB, 256>>>(p_encproj_bf, encoder_out, p_decproj, vvec, mask,
                                      p_xbuf, DENC + HH,
                                      p_pred + (size_t)t * PCOL + HH, TT * PCOL);

        // gates0 = [context|h0] @ Wc0^T + token_gates[tok(b,t)] + b_ih0 + b_hh0
        mgemm<64, 128, 16, 32, 64>(BB, G4H, DENC + HH, p_xbuf, DENC + HH, p_Wc0,
                                   DENC + HH, p_gates, G4H,
                                   p_tokg, G4H, b_ih0, b_hh0,
                                   p_tokens + t, TT);
        lstm_cell_kernel<<<(BB * HH) / 256, 256>>>(p_gates, p_c0,
                                                   p_x1buf, HH + HH,
                                                   p_xbuf + DENC, DENC + HH);

        // gates1 = [h0n|h1] @ Wc1^T + b_ih1 + b_hh1
        mgemm<64, 128, 16, 32, 64>(BB, G4H, HH + HH, p_x1buf, HH + HH, p_Wc1, HH + HH,
                                   p_gates, G4H, nullptr, 0, b_ih1, b_hh1);
        lstm_cell_kernel<<<(BB * HH) / 256, 256>>>(p_gates, p_c1,
                                                   p_x1buf + HH, HH + HH,
                                                   p_pred + (size_t)t * PCOL, TT * PCOL);
    }

    // logits: out = [h1n|context] @ W_out[:, :H+DENC]^T + token_preds[tok(b,t)]
    mgemm<128, 128, 16, 64, 32>(BB * TT, VV, PCOL, p_pred, PCOL, W_out, HH + DENC + EE,
                                out, VV, p_tokp, VV, nullptr, nullptr,
                                p_tokens, 1);
}

// round 11
// speedup vs baseline: 1.5871x; 1.2226x over previous
#include <cuda_runtime.h>
#include <cuda_bf16.h>
#include <math.h>
#include <stdint.h>

#define BB 512
#define SS 64
#define TT 32
#define VV 128
#define EE 256
#define HH 512
#define DENC 1024
#define G4H 2048
#define EOS_IDX 2
#define PCOL (HH + DENC)  /* 1536 */

// ---------------- scratch (device globals; no allocations) ----------------
__device__ __nv_bfloat16 g_encproj_bf[(size_t)BB * SS * HH];  // 32 MB (score path)
__device__ float g_pred[(size_t)BB * TT * PCOL];       // 100 MB  [h1n | context] (tf32-rounded)
__device__ float g_Wc0[G4H * (DENC + HH)];             // rounded [W_ih0[:,E:] | W_hh0]
__device__ float g_Wc1[G4H * (HH + HH)];               // rounded [W_ih1 | W_hh1]
__device__ float g_Wdec_r[HH * HH];                    // rounded W_dec
__device__ float g_Wenc_r[HH * DENC];                  // rounded W_enc
__device__ float g_Wout_r[VV * PCOL];                  // rounded compact W_out[:, :PCOL]
__device__ float g_token_gates[VV * G4H];              // per-token W_ih0[:, :E] @ emb
__device__ float g_token_preds[VV * VV];               // per-token W_out emb part + b_out
__device__ int   g_tokens[BB * TT];                    // input token per (b,t)
__device__ float g_xbuf[BB * (DENC + HH)];             // [context | h0] (tf32-rounded)
__device__ float g_x1buf[BB * (HH + HH)];              // [h0n | h1] (tf32-rounded)
__device__ float g_gates[BB * G4H];
__device__ float g_c0buf[BB * HH];
__device__ float g_c1buf[BB * HH];
__device__ float g_decproj[BB * HH];

__device__ __forceinline__ float sigmoid_fast(float x) {
    return __fdividef(1.0f, 1.0f + __expf(-x));
}
__device__ __forceinline__ float tanh_hw(float x) {
    float y;
    asm("tanh.approx.f32 %0, %1;" : "=f"(y) : "f"(x));
    return y;
}

__device__ __forceinline__ uint32_t f2tf32(float x) {
    uint32_t r;
    asm("cvt.rna.tf32.f32 %0, %1;" : "=r"(r) : "f"(x));
    return r;
}
__device__ __forceinline__ float tf32r(float x) { return __uint_as_float(f2tf32(x)); }

__device__ __forceinline__ uint32_t smem_u32(const void* p) {
    return (uint32_t)__cvta_generic_to_shared(p);
}
__device__ __forceinline__ void cp_async16(void* smem, const void* gmem) {
    asm volatile("cp.async.cg.shared.global [%0], [%1], 16;"
                 :: "r"(smem_u32(smem)), "l"(gmem));
}
__device__ __forceinline__ void cp_commit() {
    asm volatile("cp.async.commit_group;");
}
template <int N>
__device__ __forceinline__ void cp_wait() {
    asm volatile("cp.async.wait_group %0;" :: "n"(N));
}

__device__ __forceinline__ void mma_tf32(float* c, const uint32_t* a, const uint32_t* b) {
    asm volatile(
        "mma.sync.aligned.m16n8k8.row.col.f32.tf32.tf32.f32 "
        "{%0,%1,%2,%3},{%4,%5,%6,%7},{%8,%9},{%0,%1,%2,%3};"
        : "+f"(c[0]), "+f"(c[1]), "+f"(c[2]), "+f"(c[3])
        : "r"(a[0]), "r"(a[1]), "r"(a[2]), "r"(a[3]), "r"(b[0]), "r"(b[1]));
}

// ---------------- TF32 tensor-core NT GEMM, multi-stage cp.async, 1 sync/tile --------
// C[M,N] = A(MxK) * B(NxK)^T  (+bias0[n]+bias1[n]+Cin[row', n]; optional += C; bf16 out)
// APRE/BPRE: operand is already tf32-rounded -> skip cvt (bit-exact identity).
template <int BM, int BN, int BK, int WM, int WN, int STAGES, bool APRE, bool BPRE>
__global__ void __launch_bounds__((BM / WM) * (BN / WN) * 32,
                                  512 / ((BM / WM) * (BN / WN) * 32))
mma_nt_kernel(int M, int N, int K,
              const float* __restrict__ A, int lda,
              const float* __restrict__ B, int ldb,
              void* __restrict__ Cv, int ldc,
              const float* __restrict__ Cin, int ldcin,
              const float* __restrict__ bias0,
              const float* __restrict__ bias1,
              const int* __restrict__ rowtok, int rts,
              int accumulate, int out_bf16) {
    constexpr int WARPS_M = BM / WM, WARPS_N = BN / WN;
    constexpr int NW = WARPS_M * WARPS_N, THREADS = NW * 32;
    constexpr int MI = WM / 16, NI = WN / 8, KI = BK / 8;
    constexpr int LDS_ = BK + 4;  // stride 20 words: conflict-free
    constexpr int A_CP = BM * (BK / 4) / THREADS;
    constexpr int B_CP = BN * (BK / 4) / THREADS;

    __shared__ __align__(16) float As[STAGES][BM][LDS_];
    __shared__ __align__(16) float Bs[STAGES][BN][LDS_];

    const int tid = threadIdx.x;
    const int wid = tid >> 5, lane = tid & 31;
    const int wm = (wid / WARPS_N) * WM, wn = (wid % WARPS_N) * WN;
    const int g = lane >> 2, tg = lane & 3;
    const int bm = blockIdx.y * BM, bn = blockIdx.x * BN;

    float acc[MI][NI][4];
#pragma unroll
    for (int i = 0; i < MI; i++)
#pragma unroll
        for (int j = 0; j < NI; j++)
#pragma unroll
            for (int q = 0; q < 4; q++) acc[i][j][q] = 0.0f;

    auto issue_tile = [&](int tile, int slot) {
        const int k0 = tile * BK;
#pragma unroll
        for (int i = 0; i < A_CP; i++) {
            int idx = tid + i * THREADS;
            int m = idx / (BK / 4), kq = (idx % (BK / 4)) * 4;
            cp_async16(&As[slot][m][kq], A + (size_t)(bm + m) * lda + k0 + kq);
        }
#pragma unroll
        for (int i = 0; i < B_CP; i++) {
            int idx = tid + i * THREADS;
            int n = idx / (BK / 4), kq = (idx % (BK / 4)) * 4;
            cp_async16(&Bs[slot][n][kq], B + (size_t)(bn + n) * ldb + k0 + kq);
        }
    };

    const int ntiles = K / BK;
#pragma unroll
    for (int s = 0; s < STAGES - 1; s++) {
        issue_tile(s, s);
        cp_commit();
    }

    for (int t = 0; t < ntiles; t++) {
        cp_wait<STAGES - 2>();
        __syncthreads();  // sole barrier: also protects the slot refilled below
        const int slot = t % STAGES;

#pragma unroll
        for (int ki = 0; ki < KI; ki++) {
            const int k_lo = ki * 8 + tg, k_hi = k_lo + 4;
            uint32_t af[MI][4];
            uint32_t bfv[NI][2];
#pragma unroll
            for (int mi = 0; mi < MI; mi++) {
                const int mr = wm + mi * 16 + g;
                if (APRE) {
                    af[mi][0] = __float_as_uint(As[slot][mr][k_lo]);
                    af[mi][1] = __float_as_uint(As[slot][mr + 8][k_lo]);
                    af[mi][2] = __float_as_uint(As[slot][mr][k_hi]);
                    af[mi][3] = __float_as_uint(As[slot][mr + 8][k_hi]);
                } else {
                    af[mi][0] = f2tf32(As[slot][mr][k_lo]);
                    af[mi][1] = f2tf32(As[slot][mr + 8][k_lo]);
                    af[mi][2] = f2tf32(As[slot][mr][k_hi]);
                    af[mi][3] = f2tf32(As[slot][mr + 8][k_hi]);
                }
            }
#pragma unroll
            for (int ni = 0; ni < NI; ni++) {
                const int nr = wn + ni * 8 + g;
                if (BPRE) {
                    bfv[ni][0] = __float_as_uint(Bs[slot][nr][k_lo]);
                    bfv[ni][1] = __float_as_uint(Bs[slot][nr][k_hi]);
                } else {
                    bfv[ni][0] = f2tf32(Bs[slot][nr][k_lo]);
                    bfv[ni][1] = f2tf32(Bs[slot][nr][k_hi]);
                }
            }
#pragma unroll
            for (int mi = 0; mi < MI; mi++)
#pragma unroll
                for (int ni = 0; ni < NI; ni++) mma_tf32(acc[mi][ni], af[mi], bfv[ni]);
        }

        if (t + STAGES - 1 < ntiles) issue_tile(t + STAGES - 1, (t + STAGES - 1) % STAGES);
        cp_commit();
    }

    // epilogue
#pragma unroll
    for (int mi = 0; mi < MI; mi++) {
#pragma unroll
        for (int ni = 0; ni < NI; ni++) {
            const int col = bn + wn + ni * 8 + tg * 2;
#pragma unroll
            for (int half = 0; half < 2; half++) {
                const int row = bm + wm + mi * 16 + g + half * 8;
                float v0 = acc[mi][ni][half * 2 + 0];
                float v1 = acc[mi][ni][half * 2 + 1];
                if (out_bf16) {
                    __nv_bfloat162* cp =
                        (__nv_bfloat162*)((__nv_bfloat16*)Cv + (size_t)row * ldc + col);
                    *cp = __float22bfloat162_rn(make_float2(v0, v1));
                    continue;
                }
                float* C = (float*)Cv;
                if (bias0) { v0 += bias0[col]; v1 += bias0[col + 1]; }
                if (bias1) { v0 += bias1[col]; v1 += bias1[col + 1]; }
                if (Cin) {
                    const int crow = rowtok ? rowtok[row * rts] : row;
                    float2 ci = *(const float2*)(Cin + (size_t)crow * ldcin + col);
                    v0 += ci.x; v1 += ci.y;
                }
                float2* cp = (float2*)(C + (size_t)row * ldc + col);
                if (accumulate) {
                    float2 c = *cp;
                    v0 += c.x; v1 += c.y;
                }
                *cp = make_float2(v0, v1);
            }
        }
    }
}

template <int BM, int BN, int BK, int WM, int WN, int STAGES, bool APRE, bool BPRE>
static void mgemm(int M, int N, int K,
                  const float* A, int lda, const float* B, int ldb,
                  void* C, int ldc,
                  const float* Cin = nullptr, int ldcin = 0,
                  const float* bias0 = nullptr, const float* bias1 = nullptr,
                  const int* rowtok = nullptr, int rts = 1,
                  bool accumulate = false, bool out_bf16 = false) {
    dim3 grid(N / BN, M / BM);
    mma_nt_kernel<BM, BN, BK, WM, WN, STAGES, APRE, BPRE>
        <<<grid, (BM / WM) * (BN / WN) * 32>>>(
            M, N, K, A, lda, B, ldb, C, ldc, Cin, ldcin, bias0, bias1, rowtok, rts,
            accumulate ? 1 : 0, out_bf16 ? 1 : 0);
}

// ---------------- precompute kernels ----------------
__global__ void tokens_kernel(const int* __restrict__ targets, int* __restrict__ toks) {
    int idx = blockIdx.x * blockDim.x + threadIdx.x;  // B*T
    int t = idx & (TT - 1);
    int b = idx >> 5;
    toks[idx] = (t == 0) ? EOS_IDX : targets[b * TT + t - 1];
}

// combined weights, tf32-pre-rounded
__global__ void build_wcomb_kernel(const float* __restrict__ W_ih0,
                                   const float* __restrict__ W_hh0,
                                   const float* __restrict__ W_ih1,
                                   const float* __restrict__ W_hh1,
                                   float* __restrict__ Wc0,
                                   float* __restrict__ Wc1) {
    int idx = blockIdx.x * blockDim.x + threadIdx.x;
    const int N0 = G4H * (DENC + HH);
    const int N1 = G4H * (HH + HH);
    if (idx < N0) {
        int n = idx / (DENC + HH);
        int k = idx % (DENC + HH);
        float v = (k < DENC) ? W_ih0[(size_t)n * (EE + DENC) + EE + k]
                             : W_hh0[(size_t)n * HH + (k - DENC)];
        Wc0[idx] = tf32r(v);
    } else if (idx < N0 + N1) {
        int r = idx - N0;
        int n = r / (HH + HH);
        int k = r % (HH + HH);
        float v = (k < HH) ? W_ih1[(size_t)n * HH + k]
                           : W_hh1[(size_t)n * HH + (k - HH)];
        Wc1[r] = tf32r(v);
    }
}

// rounded copies of W_dec, W_enc, compact W_out[:, :PCOL]
__global__ void round_weights_kernel(const float* __restrict__ W_dec,
                                     const float* __restrict__ W_enc,
                                     const float* __restrict__ W_out,
                                     float* __restrict__ Wdec_r,
                                     float* __restrict__ Wenc_r,
                                     float* __restrict__ Wout_r) {
    int idx = blockIdx.x * blockDim.x + threadIdx.x;
    const int N0 = HH * HH;
    const int N1 = HH * DENC;
    const int N2 = VV * PCOL;
    if (idx < N0) {
        Wdec_r[idx] = tf32r(W_dec[idx]);
    } else if (idx < N0 + N1) {
        int r = idx - N0;
        Wenc_r[r] = tf32r(W_enc[r]);
    } else if (idx < N0 + N1 + N2) {
        int r = idx - N0 - N1;
        int row = r / PCOL, col = r % PCOL;
        Wout_r[r] = tf32r(W_out[(size_t)row * (HH + DENC + EE) + col]);
    }
}

__global__ void init_state_kernel(const float* __restrict__ h0,
                                  const float* __restrict__ c0,
                                  float* __restrict__ xbuf,
                                  float* __restrict__ x1buf,
                                  float* __restrict__ cb0,
                                  float* __restrict__ cb1) {
    int idx = blockIdx.x * blockDim.x + threadIdx.x;  // B*H
    int b = idx >> 9;
    int h = idx & (HH - 1);
    xbuf[(size_t)b * (DENC + HH) + DENC + h] = tf32r(h0[idx]);
    x1buf[(size_t)b * (HH + HH) + HH + h] = tf32r(h0[(size_t)BB * HH + idx]);
    cb0[idx] = c0[idx];
    cb1[idx] = c0[(size_t)BB * HH + idx];
}

// ---------------- attention (fused score/tanh + masked softmax + context) ----------------
__global__ void __launch_bounds__(256) attention_kernel(
    const __nv_bfloat16* __restrict__ enc_proj,   // (B,S,H) bf16
    const float* __restrict__ enc,        // (B,S,DENC) fp32
    const float* __restrict__ decp,       // (B,H)
    const float* __restrict__ vvec,       // (H)
    const int* __restrict__ mask,         // (B,S)
    float* __restrict__ ctx_dst1, int ld1,
    float* __restrict__ ctx_dst2, int ld2) {
    const int b = blockIdx.x;
    __shared__ float s_dp[HH];
    __shared__ float s_v[HH];
    __shared__ float s_w[SS];
    __shared__ float s_red[2];
    const int tid = threadIdx.x;
    const int warp = tid >> 5, lane = tid & 31;

    for (int i = tid; i < HH; i += 256) {
        s_dp[i] = decp[(size_t)b * HH + i];
        s_v[i] = vvec[i];
    }
    __syncthreads();

    for (int s = warp; s < SS; s += 8) {
        const __nv_bfloat162* ep =
            (const __nv_bfloat162*)(enc_proj + ((size_t)b * SS + s) * HH);
        float acc = 0.0f;
#pragma unroll 4
        for (int h2 = lane; h2 < HH / 2; h2 += 32) {
            float2 e = __bfloat1622float2(ep[h2]);
            acc += s_v[2 * h2] * tanh_hw(s_dp[2 * h2] + e.x);
            acc += s_v[2 * h2 + 1] * tanh_hw(s_dp[2 * h2 + 1] + e.y);
        }
#pragma unroll
        for (int o = 16; o; o >>= 1) acc += __shfl_xor_sync(0xffffffffu, acc, o);
        if (lane == 0) s_w[s] = mask[b * SS + s] ? acc : -1e30f;
    }
    __syncthreads();

    if (warp == 0) {
        float m = fmaxf(s_w[lane], s_w[lane + 32]);
#pragma unroll
        for (int o = 16; o; o >>= 1) m = fmaxf(m, __shfl_xor_sync(0xffffffffu, m, o));
        float sum = __expf(s_w[lane] - m) + __expf(s_w[lane + 32] - m);
#pragma unroll
        for (int o = 16; o; o >>= 1) sum += __shfl_xor_sync(0xffffffffu, sum, o);
        if (lane == 0) { s_red[0] = m; s_red[1] = sum; }
    }
    __syncthreads();
    const float m = s_red[0], inv = 1.0f / s_red[1];
    if (tid < SS) s_w[tid] = __expf(s_w[tid] - m) * inv;
    __syncthreads();

    // context: thread tid owns float4 d-chunk; store tf32-rounded (consumers cvt anyway)
    const float4* eb4 = (const float4*)(enc + (size_t)b * SS * DENC);
    float4 acc4 = make_float4(0.f, 0.f, 0.f, 0.f);
#pragma unroll 8
    for (int s = 0; s < SS; s++) {
        const float w = s_w[s];
        float4 e = eb4[(size_t)s * (DENC / 4) + tid];
        acc4.x += w * e.x; acc4.y += w * e.y;
        acc4.z += w * e.z; acc4.w += w * e.w;
    }
    acc4.x = tf32r(acc4.x); acc4.y = tf32r(acc4.y);
    acc4.z = tf32r(acc4.z); acc4.w = tf32r(acc4.w);
    *(float4*)(ctx_dst1 + (size_t)b * ld1 + 4 * tid) = acc4;
    *(float4*)(ctx_dst2 + (size_t)b * ld2 + 4 * tid) = acc4;
}

// ---------------- LSTM pointwise cell (plain gate layout) ----------------
__global__ void lstm_cell_kernel(const float* __restrict__ gates,  // (B,4H)
                                 float* __restrict__ c,            // (B,H) in/out
                                 float* __restrict__ hA, int ldA,
                                 float* __restrict__ hB, int ldB) {
    int idx = blockIdx.x * blockDim.x + threadIdx.x;  // B*H
    int b = idx >> 9;
    int h = idx & (HH - 1);
    const float* g = gates + (size_t)b * G4H;
    float ig = sigmoid_fast(g[h]);
    float fg = sigmoid_fast(g[HH + h]);
    float gg = tanhf(g[2 * HH + h]);
    float og = sigmoid_fast(g[3 * HH + h]);
    float cn = fg * c[idx] + ig * gg;
    c[idx] = cn;
    float hn = tf32r(og * tanhf(cn));  // consumers apply tf32 cvt anyway: bit-exact
    hA[(size_t)b * ldA + h] = hn;
    hB[(size_t)b * ldB + h] = hn;
}

// ---------------- host ----------------
extern "C" void kernel_launch(void* const* d_in, const int* in_sizes, int n_in,
                              void* d_out, int out_size) {
    const float* encoder_out = (const float*)d_in[0];
    const float* h0   = (const float*)d_in[1];
    const float* c0   = (const float*)d_in[2];
    const int*   targets = (const int*)d_in[3];
    const int*   mask    = (const int*)d_in[4];
    const float* emb   = (const float*)d_in[5];
    const float* W_enc = (const float*)d_in[6];
    const float* W_dec = (const float*)d_in[7];
    const float* vvec  = (const float*)d_in[8];
    const float* W_ih0 = (const float*)d_in[9];
    const float* W_hh0 = (const float*)d_in[10];
    const float* b_ih0 = (const float*)d_in[11];
    const float* b_hh0 = (const float*)d_in[12];
    const float* W_ih1 = (const float*)d_in[13];
    const float* W_hh1 = (const float*)d_in[14];
    const float* b_ih1 = (const float*)d_in[15];
    const float* b_hh1 = (const float*)d_in[16];
    const float* W_out = (const float*)d_in[17];
    const float* b_out = (const float*)d_in[18];
    float* out = (float*)d_out;  // (B,T,V)

    __nv_bfloat16* p_encproj_bf;
    float *p_pred, *p_Wc0, *p_Wc1, *p_Wdec, *p_Wenc, *p_Wout, *p_tokg, *p_tokp;
    float *p_xbuf, *p_x1buf, *p_gates, *p_c0, *p_c1, *p_decproj;
    int* p_tokens;
    cudaGetSymbolAddress((void**)&p_encproj_bf, g_encproj_bf);
    cudaGetSymbolAddress((void**)&p_pred, g_pred);
    cudaGetSymbolAddress((void**)&p_Wc0, g_Wc0);
    cudaGetSymbolAddress((void**)&p_Wc1, g_Wc1);
    cudaGetSymbolAddress((void**)&p_Wdec, g_Wdec_r);
    cudaGetSymbolAddress((void**)&p_Wenc, g_Wenc_r);
    cudaGetSymbolAddress((void**)&p_Wout, g_Wout_r);
    cudaGetSymbolAddress((void**)&p_tokg, g_token_gates);
    cudaGetSymbolAddress((void**)&p_tokp, g_token_preds);
    cudaGetSymbolAddress((void**)&p_tokens, g_tokens);
    cudaGetSymbolAddress((void**)&p_xbuf, g_xbuf);
    cudaGetSymbolAddress((void**)&p_x1buf, g_x1buf);
    cudaGetSymbolAddress((void**)&p_gates, g_gates);
    cudaGetSymbolAddress((void**)&p_c0, g_c0buf);
    cudaGetSymbolAddress((void**)&p_c1, g_c1buf);
    cudaGetSymbolAddress((void**)&p_decproj, g_decproj);

    // ---- precompute ----
    tokens_kernel<<<(BB * TT) / 256, 256>>>(targets, p_tokens);
    {
        int total = G4H * (DENC + HH) + G4H * (HH + HH);
        build_wcomb_kernel<<<(total + 255) / 256, 256>>>(W_ih0, W_hh0, W_ih1, W_hh1,
                                                         p_Wc0, p_Wc1);
    }
    {
        int total = HH * HH + HH * DENC + VV * PCOL;
        round_weights_kernel<<<(total + 255) / 256, 256>>>(W_dec, W_enc, W_out,
                                                           p_Wdec, p_Wenc, p_Wout);
    }
    init_state_kernel<<<(BB * HH) / 256, 256>>>(h0, c0, p_xbuf, p_x1buf, p_c0, p_c1);

    // token_gates (V,4H) = emb @ W_ih0[:, :E]^T   (raw operands)
    mgemm<64, 128, 16, 32, 64, 4, false, false>(VV, G4H, EE, emb, EE, W_ih0, EE + DENC,
                                                p_tokg, G4H);
    // token_preds (V,V) = emb @ W_out[:, H+DENC:]^T + b_out
    mgemm<64, 64, 16, 32, 32, 4, false, false>(VV, VV, EE, emb, EE,
                                               W_out + (HH + DENC), HH + DENC + EE,
                                               p_tokp, VV, nullptr, 0, b_out);
    // enc_proj -> bf16 (score path only); B pre-rounded
    mgemm<128, 128, 16, 64, 32, 3, false, true>(BB * SS, HH, DENC, encoder_out, DENC,
                                                p_Wenc, DENC, p_encproj_bf, HH,
                                                nullptr, 0, nullptr, nullptr,
                                                nullptr, 1, false, true);

    // ---- sequential decode ----
    for (int t = 0; t < TT; t++) {
        // dec_proj = h1 @ Wdec_r^T   (both operands pre-rounded)
        mgemm<64, 64, 16, 32, 32, 4, true, true>(BB, HH, HH, p_x1buf + HH, HH + HH,
                                                 p_Wdec, HH, p_decproj, HH);

        // attention: context -> xbuf[:, :DENC] and pred[:, t, H:]
        attention_kernel<<<BB, 256>>>(p_encproj_bf, encoder_out, p_decproj, vvec, mask,
                                      p_xbuf, DENC + HH,
                                      p_pred + (size_t)t * PCOL + HH, TT * PCOL);

        // gates0 = [context|h0] @ Wc0^T + token_gates[tok(b,t)] + b_ih0 + b_hh0
        mgemm<64, 128, 16, 32, 64, 4, true, true>(BB, G4H, DENC + HH, p_xbuf, DENC + HH,
                                                  p_Wc0, DENC + HH, p_gates, G4H,
                                                  p_tokg, G4H, b_ih0, b_hh0,
                                                  p_tokens + t, TT);
        lstm_cell_kernel<<<(BB * HH) / 256, 256>>>(p_gates, p_c0,
                                                   p_x1buf, HH + HH,
                                                   p_xbuf + DENC, DENC + HH);

        // gates1 = [h0n|h1] @ Wc1^T + b_ih1 + b_hh1
        mgemm<64, 128, 16, 32, 64, 4, true, true>(BB, G4H, HH + HH, p_x1buf, HH + HH,
                                                  p_Wc1, HH + HH, p_gates, G4H,
                                                  nullptr, 0, b_ih1, b_hh1);
        lstm_cell_kernel<<<(BB * HH) / 256, 256>>>(p_gates, p_c1,
                                                   p_x1buf + HH, HH + HH,
                                                   p_pred + (size_t)t * PCOL, TT * PCOL);
    }

    // logits: out = [h1n|context] @ Wout_r^T + token_preds[tok(b,t)]  (A,B pre-rounded)
    mgemm<128, 128, 16, 64, 32, 3, true, true>(BB * TT, VV, PCOL, p_pred, PCOL,
                                               p_Wout, PCOL, out, VV,
                                               p_tokp, VV, nullptr, nullptr,
                                               p_tokens, 1);
}